// round 17
// baseline (speedup 1.0000x reference)
#include <cuda_runtime.h>
#include <cuda_bf16.h>
#include <cuda_fp16.h>
#include <cstdint>
#include <cstring>

// Problem constants
#define B_   2
#define C_   64
#define H_   192
#define W_   192
#define HW_  (H_*W_)          // 36864
#define KK_  9
#define HP_  194
#define WP_  194
#define HPWP_ (HP_*WP_)       // 37636
#define CI_  65               // C+1
#define OC_  18               // 2*KK

// Scratch (device globals)
__device__ __half   g_xp  [B_*HPWP_*C_];     // padded x, NHWC fp16 (~9.6 MB)
__device__ float    g_dp  [B_*HPWP_];        // padded depth (~0.3 MB)
__device__ float    g_off [B_*OC_*HW_];      // offsets (~5.3 MB)
__device__ uint16_t g_wtbh[KK_*C_*C_];       // fused weight hi fp16, [kk][oc][c]
__device__ uint16_t g_wtbl[KK_*C_*C_];       // fused weight lo fp16
__device__ uint16_t g_wobh[10*32*C_];        // offconv weight hi fp16
__device__ uint16_t g_wobl[10*32*C_];        // offconv weight lo fp16

// ---------------------------------------------------------------------------
// helpers
// ---------------------------------------------------------------------------
__device__ __forceinline__ uint2 f4_to_h4(float4 v) {
    __half2 h0 = __floats2half2_rn(v.x, v.y);
    __half2 h1 = __floats2half2_rn(v.z, v.w);
    uint2 r;
    memcpy(&r.x, &h0, 4);
    memcpy(&r.y, &h1, 4);
    return r;
}

// f16 mma: D(f32) += A(f16) * B(f16)
__device__ __forceinline__ void mma16816(float& d0, float& d1, float& d2, float& d3,
                                         uint32_t a0, uint32_t a1, uint32_t a2, uint32_t a3,
                                         uint32_t b0, uint32_t b1) {
    asm volatile("mma.sync.aligned.m16n8k16.row.col.f32.f16.f16.f32 "
                 "{%0,%1,%2,%3},{%4,%5,%6,%7},{%8,%9},{%0,%1,%2,%3};"
                 : "+f"(d0), "+f"(d1), "+f"(d2), "+f"(d3)
                 : "r"(a0), "r"(a1), "r"(a2), "r"(a3), "r"(b0), "r"(b1));
}

__device__ __forceinline__ void fp16_split(float v, uint16_t& h, uint16_t& l) {
    __half hb = __float2half_rn(v);
    float hf = __half2float(hb);
    __half lb = __float2half_rn(v - hf);
    memcpy(&h, &hb, 2); memcpy(&l, &lb, 2);
}

// half2 lerp: r = a*(y-x) + x
__device__ __forceinline__ __half2 h2lerp(__half2 a, __half2 x, __half2 y) {
    return __hfma2(a, __hsub2(y, x), x);
}

// ---------------------------------------------------------------------------
// Kernel 1: merged prep + NHWC transpose (partitioned 1-D grid).
// blocks [0, 2304):   NCHW fp32 -> padded NHWC fp16 transpose
// blocks [2304, ...): job = (bx-2304)/295:
//   job 0: zero border of g_xp; job 1: fused weights fp16 hi/lo;
//   job 2: offconv GEMM weights; job 3: padded depth plane.
// ---------------------------------------------------------------------------
#define NBORD_ (2*WP_ + 2*(HP_-2))   // 772
#define NHWCB_ (1152 * B_)           // 2304
__global__ __launch_bounds__(256) void prep_kernel(
    const float* __restrict__ x,
    const float* __restrict__ w,
    const float* __restrict__ w_off,
    const float* __restrict__ depth)
{
    __shared__ float tile[C_][33];
    const int bx  = blockIdx.x;
    const int tid = threadIdx.x;

    if (bx < NHWCB_) {
        // --- NHWC transpose ---
        const int b    = bx / 1152;
        const int pix0 = (bx % 1152) * 32;
        {
            int ty = tid >> 5, tx = tid & 31;
            #pragma unroll
            for (int c0 = 0; c0 < C_; c0 += 8)
                tile[c0 + ty][tx] = x[((size_t)b * C_ + c0 + ty) * HW_ + pix0 + tx];
        }
        __syncthreads();
        {
            int pi = tid >> 6, c = tid & 63;
            #pragma unroll
            for (int j = 0; j < 8; ++j) {
                int pix = pix0 + j * 4 + pi;
                int ph = pix / W_ + 1, pw = pix % W_ + 1;
                g_xp[((size_t)b * HPWP_ + ph * WP_ + pw) * C_ + c] =
                    __float2half(tile[c][j * 4 + pi]);
            }
        }
        return;
    }

    const int j   = bx - NHWCB_;
    const int job = j / 295;
    const int i   = (j % 295) * 256 + tid;

    if (job == 0) {
        if (i >= B_ * NBORD_ * 8) return;
        int b   = i / (NBORD_ * 8);
        int r   = i % (NBORD_ * 8);
        int pix = r >> 3;
        int cq  = r & 7;
        int ph, pw;
        if (pix < WP_)            { ph = 0;        pw = pix; }
        else if (pix < 2*WP_)     { ph = HP_ - 1;  pw = pix - WP_; }
        else if (pix < 2*WP_ + (HP_-2)) { ph = pix - 2*WP_ + 1;  pw = 0; }
        else                      { ph = pix - (2*WP_ + (HP_-2)) + 1; pw = WP_ - 1; }
        reinterpret_cast<float4*>(g_xp + ((size_t)b * HPWP_ + ph * WP_ + pw) * C_)[cq] =
            make_float4(0.f, 0.f, 0.f, 0.f);
    } else if (job == 1) {
        if (i >= KK_*C_*C_) return;
        int kk = i / (C_*C_);
        int oc = (i >> 6) & 63;
        int c  = i & 63;
        float v = w[oc * 576 + c * KK_ + kk];
        uint16_t hb, lb; fp16_split(v, hb, lb);
        g_wtbh[(kk * C_ + oc) * C_ + c] = hb;
        g_wtbl[(kk * C_ + oc) * C_ + c] = lb;
    } else if (job == 2) {
        if (i >= 10*32*C_) return;
        int ch = i / (32*C_);
        int r  = i % (32*C_);
        int oc = r >> 6;
        int k  = r & 63;
        float v = 0.f;
        if (oc < OC_) {
            if (ch < 9)        v = w_off[(oc * CI_ + k) * KK_ + ch];
            else if (k < KK_)  v = w_off[(oc * CI_ + 64) * KK_ + k];
        }
        uint16_t hb, lb; fp16_split(v, hb, lb);
        g_wobh[i] = hb;
        g_wobl[i] = lb;
    } else {
        if (i >= B_ * HPWP_) return;
        int b  = i / HPWP_;
        int pp = i % HPWP_;
        int ph = pp / WP_, pw = pp % WP_;
        float v = 0.f;
        if (ph >= 1 && ph <= H_ && pw >= 1 && pw <= W_)
            v = depth[(size_t)b * HW_ + (ph - 1) * W_ + (pw - 1)];
        g_dp[i] = v;
    }
}

// ---------------------------------------------------------------------------
// Kernel 2: offconv as mma.sync f16 GEMM, A double-buffered: fillA(ch+1)
// overlaps mma(ch) in-stream. Block 128 px x 24 oc, 256 threads.
// ---------------------------------------------------------------------------
#define APITCH_ 72
#define OATILE_ (128 * APITCH_)

__global__ __launch_bounds__(256) void offmma_kernel(const float* __restrict__ bias)
{
    __shared__ __align__(16) uint16_t Aa [2 * OATILE_];   // 36864 B
    __shared__ __align__(16) uint16_t Bhi[32 * APITCH_];  //  4608 B
    __shared__ __align__(16) uint16_t Blo[32 * APITCH_];  //  4608 B

    const int tid  = threadIdx.x;
    const int wid  = tid >> 5;
    const int lane = tid & 31;
    const int b    = blockIdx.y;
    const int pix0 = blockIdx.x * 128;

    const __half* xb = g_xp + (size_t)b * HPWP_ * C_;
    const float*  db = g_dp + (size_t)b * HPWP_;
    const int cg = tid & 15;    // channel group (4 ch)
    const int pb = tid >> 4;    // 0..15

    auto fillA = [&](int ch, int buf) {
        uint16_t* A = Aa + buf * OATILE_;
        if (ch < 9) {
            const int dy = ch / 3, dx = ch % 3;
            #pragma unroll 2
            for (int i = 0; i < 8; ++i) {
                int p = pb + 16 * i;
                int pix = pix0 + p;
                int oh = pix / W_, ow = pix % W_;
                int idx = (oh + dy) * WP_ + (ow + dx);
                const uint2* q = reinterpret_cast<const uint2*>(xb + (size_t)idx * C_) + cg;
                *reinterpret_cast<uint2*>(&A[p * APITCH_ + cg * 4]) = q[0];
            }
        } else {
            if (cg >= 4) return;
            #pragma unroll 2
            for (int i = 0; i < 8; ++i) {
                int p = pb + 16 * i;
                int pix = pix0 + p;
                int oh = pix / W_, ow = pix % W_;
                float4 v = make_float4(0.f, 0.f, 0.f, 0.f);
                float* ve = &v.x;
                #pragma unroll
                for (int e = 0; e < 4; ++e) {
                    int t = cg * 4 + e;
                    if (t < KK_)
                        ve[e] = db[(oh + t / 3) * WP_ + (ow + t % 3)];
                }
                *reinterpret_cast<uint2*>(&A[p * APITCH_ + cg * 4]) = f4_to_h4(v);
            }
        }
    };

    auto stageB = [&](int ch) {
        const uint2* sh = reinterpret_cast<const uint2*>(g_wobh + ch * (32*C_));
        const uint2* sl = reinterpret_cast<const uint2*>(g_wobl + ch * (32*C_));
        #pragma unroll
        for (int e = tid; e < 512; e += 256) {
            int oc = e >> 4, c4 = e & 15;
            int doff = oc * APITCH_ + c4 * 4;
            *reinterpret_cast<uint2*>(&Bhi[doff]) = sh[e];
            *reinterpret_cast<uint2*>(&Blo[doff]) = sl[e];
        }
    };

    float acc[3][4];
    #pragma unroll
    for (int ni = 0; ni < 3; ++ni)
        #pragma unroll
        for (int r = 0; r < 4; ++r) acc[ni][r] = 0.f;

    const int arow = wid * 16 + (lane >> 2);
    const int akol = (lane & 3) * 2;
    const int brow = lane >> 2;

    fillA(0, 0);
    stageB(0);
    __syncthreads();

    for (int ch = 0; ch < 10; ++ch) {
        const int buf = ch & 1;
        if (ch + 1 < 10) fillA(ch + 1, buf ^ 1);   // overlaps mma below

        const int nki = (ch == 9) ? 1 : 4;
        const uint16_t* A = Aa + buf * OATILE_;
        for (int ki = 0; ki < nki; ++ki) {
            const int k0 = ki * 16 + akol;
            const int r0 = arow * APITCH_ + k0;
            const int r1 = r0 + 8 * APITCH_;
            uint32_t a0 = *reinterpret_cast<const uint32_t*>(&A[r0]);
            uint32_t a1 = *reinterpret_cast<const uint32_t*>(&A[r1]);
            uint32_t a2 = *reinterpret_cast<const uint32_t*>(&A[r0 + 8]);
            uint32_t a3 = *reinterpret_cast<const uint32_t*>(&A[r1 + 8]);
            #pragma unroll
            for (int ni = 0; ni < 3; ++ni) {
                int boff = (brow + ni * 8) * APITCH_ + k0;
                uint32_t bh0 = *reinterpret_cast<const uint32_t*>(&Bhi[boff]);
                uint32_t bh1 = *reinterpret_cast<const uint32_t*>(&Bhi[boff + 8]);
                uint32_t bl0 = *reinterpret_cast<const uint32_t*>(&Blo[boff]);
                uint32_t bl1 = *reinterpret_cast<const uint32_t*>(&Blo[boff + 8]);
                float* d = acc[ni];
                mma16816(d[0], d[1], d[2], d[3], a0, a1, a2, a3, bh0, bh1);
                mma16816(d[0], d[1], d[2], d[3], a0, a1, a2, a3, bl0, bl1);
            }
        }
        __syncthreads();           // A(ch+1) written, mma(ch) done
        if (ch + 1 < 10) {
            stageB(ch + 1);
            __syncthreads();
        }
    }

    const int px = pix0 + wid * 16 + (lane >> 2);
    #pragma unroll
    for (int ni = 0; ni < 3; ++ni) {
        int oc = ni * 8 + (lane & 3) * 2;
        if (oc < OC_) {
            float b0 = bias[oc], b1 = bias[oc + 1];
            float* o0 = g_off + ((size_t)b * OC_ + oc) * HW_;
            float* o1 = g_off + ((size_t)b * OC_ + oc + 1) * HW_;
            o0[px]     = acc[ni][0] + b0;
            o1[px]     = acc[ni][1] + b1;
            o0[px + 8] = acc[ni][2] + b0;
            o1[px + 8] = acc[ni][3] + b1;
        }
    }
}

// ---------------------------------------------------------------------------
// Kernel 3: fused gather + f16 mma. A double-buffered; taps computed INSIDE
// the gather warp (shfl broadcast) -> no tap smem, no taps->gather sync;
// gather(kk+1) overlaps mma(kk) in the same instruction stream.
// smem: 2*A (36864) + Bhi/Blo (18432) = 55296 -> 4 blocks/SM.
// ---------------------------------------------------------------------------
#define MPX_    128
#define ATILE_  (MPX_ * APITCH_)            // 9216 uint16
#define BTILE_  (C_ * APITCH_)              // 4608 uint16
#define SM_A    0
#define SM_BHI  (2 * ATILE_ * 2)            // 36864
#define SM_BLO  (SM_BHI + BTILE_ * 2)       // 46080
#define SM_TOT  (SM_BLO + BTILE_ * 2)       // 55296

__global__ __launch_bounds__(256, 4) void fused_mma_kernel(float* __restrict__ out)
{
    extern __shared__ char sm[];
    uint16_t* Aa  = reinterpret_cast<uint16_t*>(sm + SM_A);
    uint16_t* Bhi = reinterpret_cast<uint16_t*>(sm + SM_BHI);
    uint16_t* Blo = reinterpret_cast<uint16_t*>(sm + SM_BLO);

    const int tid  = threadIdx.x;
    const int wid  = tid >> 5;
    const int lane = tid & 31;
    const int b    = blockIdx.y;
    const int pix0 = blockIdx.x * MPX_;

    const int ocg = wid & 1;
    const int pxg = wid >> 1;

    float acc[2][4][4];
    #pragma unroll
    for (int mi = 0; mi < 2; ++mi)
        #pragma unroll
        for (int ni = 0; ni < 4; ++ni)
            #pragma unroll
            for (int r = 0; r < 4; ++r) acc[mi][ni][r] = 0.f;

    const __half* xb = g_xp + (size_t)b * HPWP_ * C_;
    const int cg = tid & 15;
    const int pb = tid >> 4;

    // gather for kk into A buffer buf; taps computed in-warp (lanes 0/16) and
    // broadcast via shfl -> no smem, no cross-warp dependency.
    auto gather = [&](int kk, int buf) {
        uint16_t* A = Aa + buf * ATILE_;
        const float* offx = g_off + ((size_t)b * OC_ + kk) * HW_;
        const float* offy = g_off + ((size_t)b * OC_ + KK_ + kk) * HW_;
        const int kh = kk / 3, kw = kk % 3;
        #pragma unroll 2
        for (int i = 0; i < 8; ++i) {
            int p = pb + 16 * i;
            int idx = 0; uint32_t apk = 0;
            if ((lane & 15) == 0) {
                int pix = pix0 + p;
                int oh = pix / W_, ow = pix % W_;
                float cx = (float)(oh + kh) + offx[pix];
                float cy = (float)(ow + kw) + offy[pix];
                cx = fminf(fmaxf(cx, 0.f), (float)(HP_ - 1));
                cy = fminf(fmaxf(cy, 0.f), (float)(WP_ - 1));
                int tlx = (int)floorf(cx); tlx = min(max(tlx, 0), HP_ - 2);
                int tly = (int)floorf(cy); tly = min(max(tly, 0), WP_ - 2);
                idx = tlx * WP_ + tly;
                __half2 ah = __floats2half2_rn(cx - (float)tlx, cy - (float)tly);
                memcpy(&apk, &ah, 4);
            }
            const int src = lane & 16;
            idx = __shfl_sync(0xFFFFFFFFu, idx, src);
            apk = __shfl_sync(0xFFFFFFFFu, apk, src);
            __half2 aa; memcpy(&aa, &apk, 4);
            __half2 ax2 = __half2half2(__low2half(aa));
            __half2 ay2 = __half2half2(__high2half(aa));
            const uint2* q = reinterpret_cast<const uint2*>(xb + (size_t)idx * C_) + cg;
            uint2 u00 = q[0];
            uint2 u01 = q[16];           // +1 col = +64 halfs
            uint2 u10 = q[WP_ * 16];     // +1 row
            uint2 u11 = q[(WP_ + 1) * 16];
            __half2 c00a = *reinterpret_cast<__half2*>(&u00.x);
            __half2 c00b = *reinterpret_cast<__half2*>(&u00.y);
            __half2 c01a = *reinterpret_cast<__half2*>(&u01.x);
            __half2 c01b = *reinterpret_cast<__half2*>(&u01.y);
            __half2 c10a = *reinterpret_cast<__half2*>(&u10.x);
            __half2 c10b = *reinterpret_cast<__half2*>(&u10.y);
            __half2 c11a = *reinterpret_cast<__half2*>(&u11.x);
            __half2 c11b = *reinterpret_cast<__half2*>(&u11.y);
            __half2 r0a = h2lerp(ay2, c00a, c01a);
            __half2 r1a = h2lerp(ay2, c10a, c11a);
            __half2 va  = h2lerp(ax2, r0a, r1a);
            __half2 r0b = h2lerp(ay2, c00b, c01b);
            __half2 r1b = h2lerp(ay2, c10b, c11b);
            __half2 vb  = h2lerp(ax2, r0b, r1b);
            uint2 o;
            memcpy(&o.x, &va, 4);
            memcpy(&o.y, &vb, 4);
            *reinterpret_cast<uint2*>(&A[p * APITCH_ + cg * 4]) = o;
        }
    };

    auto stageB = [&](int kk) {
        const uint2* sh = reinterpret_cast<const uint2*>(g_wtbh + kk * (C_*C_));
        const uint2* sl = reinterpret_cast<const uint2*>(g_wtbl + kk * (C_*C_));
        #pragma unroll
        for (int e = tid; e < 1024; e += 256) {
            int oc = e >> 4, c4 = e & 15;
            int doff = oc * APITCH_ + c4 * 4;
            *reinterpret_cast<uint2*>(&Bhi[doff]) = sh[e];
            *reinterpret_cast<uint2*>(&Blo[doff]) = sl[e];
        }
    };

    gather(0, 0);
    stageB(0);
    __syncthreads();

    const int arow = pxg * 32 + (lane >> 2);
    const int akol = (lane & 3) * 2;
    const int brow = ocg * 32 + (lane >> 2);

    for (int kk = 0; kk < KK_; ++kk) {
        const int buf = kk & 1;
        // gather(kk+1) into the other A buffer — overlaps mma(kk) in-stream
        if (kk + 1 < KK_) gather(kk + 1, buf ^ 1);

        const uint16_t* A = Aa + buf * ATILE_;
        #pragma unroll
        for (int ki = 0; ki < 4; ++ki) {
            const int k0 = ki * 16 + akol;
            uint32_t a[2][4];
            #pragma unroll
            for (int mi = 0; mi < 2; ++mi) {
                int r0 = (arow + mi * 16) * APITCH_ + k0;
                int r1 = r0 + 8 * APITCH_;
                a[mi][0] = *reinterpret_cast<const uint32_t*>(&A[r0]);
                a[mi][1] = *reinterpret_cast<const uint32_t*>(&A[r1]);
                a[mi][2] = *reinterpret_cast<const uint32_t*>(&A[r0 + 8]);
                a[mi][3] = *reinterpret_cast<const uint32_t*>(&A[r1 + 8]);
            }
            #pragma unroll
            for (int ni = 0; ni < 4; ++ni) {
                int boff = (brow + ni * 8) * APITCH_ + k0;
                uint32_t bh0 = *reinterpret_cast<const uint32_t*>(&Bhi[boff]);
                uint32_t bh1 = *reinterpret_cast<const uint32_t*>(&Bhi[boff + 8]);
                uint32_t bl0 = *reinterpret_cast<const uint32_t*>(&Blo[boff]);
                uint32_t bl1 = *reinterpret_cast<const uint32_t*>(&Blo[boff + 8]);
                #pragma unroll
                for (int mi = 0; mi < 2; ++mi) {
                    float* d = acc[mi][ni];
                    mma16816(d[0], d[1], d[2], d[3],
                             a[mi][0], a[mi][1], a[mi][2], a[mi][3], bh0, bh1);
                    mma16816(d[0], d[1], d[2], d[3],
                             a[mi][0], a[mi][1], a[mi][2], a[mi][3], bl0, bl1);
                }
            }
        }
        __syncthreads();           // A(kk+1) written, mma(kk) done
        if (kk + 1 < KK_) {
            stageB(kk + 1);        // B single-buffered: fill after mma(kk)
            __syncthreads();
        }
    }

    #pragma unroll
    for (int mi = 0; mi < 2; ++mi) {
        int px = pix0 + pxg * 32 + mi * 16 + (lane >> 2);
        #pragma unroll
        for (int ni = 0; ni < 4; ++ni) {
            int oc = ocg * 32 + ni * 8 + (lane & 3) * 2;
            float* o0 = out + ((size_t)b * C_ + oc) * HW_;
            float* o1 = out + ((size_t)b * C_ + oc + 1) * HW_;
            o0[px]     = acc[mi][ni][0];
            o1[px]     = acc[mi][ni][1];
            o0[px + 8] = acc[mi][ni][2];
            o1[px + 8] = acc[mi][ni][3];
        }
    }
}

// ---------------------------------------------------------------------------
// Launch
// ---------------------------------------------------------------------------
extern "C" void kernel_launch(void* const* d_in, const int* in_sizes, int n_in,
                              void* d_out, int out_size) {
    const float* x      = (const float*)d_in[0];
    const float* depth  = (const float*)d_in[1];
    const float* w_off  = (const float*)d_in[2];
    const float* bias   = (const float*)d_in[3];
    const float* weight = (const float*)d_in[4];
    float* out = (float*)d_out;

    {
        int nblk = NHWCB_ + 4 * 295;   // 2304 nhwc + 4 prep jobs
        prep_kernel<<<nblk, 256>>>(x, weight, w_off, depth);
    }
    {
        dim3 grid(HW_ / 128, B_);
        offmma_kernel<<<grid, 256>>>(bias);
    }
    {
        static bool attr_set = false;
        if (!attr_set) {
            cudaFuncSetAttribute(fused_mma_kernel,
                                 cudaFuncAttributeMaxDynamicSharedMemorySize, SM_TOT);
            attr_set = true;
        }
        dim3 grid(HW_ / MPX_, B_);
        fused_mma_kernel<<<grid, 256, SM_TOT>>>(out);
    }
}